// round 17
// baseline (speedup 1.0000x reference)
#include <cuda_runtime.h>
#include <cuda_bf16.h>
#include <cuda_fp16.h>
#include <cstdint>

// ---------------------------------------------------------------------------
// GCNEncoder: out = GCNConv2( relu( GCNConv1(x) ) )
// Prescale: h_s = (x@W)*dinv (fp16) ; agg[d] = sum_in h_s[src] + h_s[d] (fp16);
// res = dinv[d]*agg + b.  CSR: init -> hist(dst only) -> assign(+cursor) ->
// scatter(re-decode, no intermediates).  Aggregate: warp-per-node fp16 gather.
// GEMMs: tcgen05 bf16 hi/lo split (fp32 or fp16 input) / FFMA fallback.
// ---------------------------------------------------------------------------

#define NMAX 100000
#define EMAX 1600000
#define D0 128
#define D1 128
#define D2 64

#if defined(__CUDA_ARCH_FEAT_SM103_ALL) || defined(__CUDA_ARCH_FEAT_SM100_ALL) || \
    (defined(__CUDA_ARCH_SPECIFIC__) && (__CUDA_ARCH__ >= 1000))
#define HAS_TCGEN05 1
#else
#define HAS_TCGEN05 0
#endif

__device__ float  g_dinv[NMAX];
__device__ __half g_h[(size_t)NMAX * D1];     // fp16 transform output
__device__ __half g_agg[(size_t)NMAX * D1];   // fp16 layer-1 result
__device__ int    g_sorted[EMAX];
__device__ int    g_cnt[NMAX];
__device__ int    g_rowptr[NMAX];
__device__ int    g_cur[NMAX];
__device__ int    g_cursor;
__device__ int    g_idx64;

// ---------------------------------------------------------------------------
// PTX helpers
// ---------------------------------------------------------------------------
__device__ __forceinline__ uint32_t smem_u32(const void* p) {
    uint32_t a;
    asm("{ .reg .u64 t; cvta.to.shared.u64 t, %1; cvt.u32.u64 %0, t; }"
        : "=r"(a) : "l"(p));
    return a;
}

#if HAS_TCGEN05
__device__ __forceinline__ uint32_t elect1() {
    uint32_t p;
    asm volatile("{ .reg .pred p; elect.sync _|p, 0xFFFFFFFF; selp.b32 %0,1,0,p; }"
                 : "=r"(p));
    return p;
}

#define TC_ALLOC(smem_addr, ncols) \
    asm volatile("tcgen05.alloc.cta_group::1.sync.aligned.shared::cta.b32 [%0], %1;" \
                 :: "r"(smem_addr), "r"(ncols) : "memory")
#define TC_DEALLOC(tmem, ncols) \
    asm volatile("tcgen05.dealloc.cta_group::1.sync.aligned.b32 %0, %1;" \
                 :: "r"(tmem), "r"(ncols))
#define TC_COMMIT(mbar) \
    asm volatile("tcgen05.commit.cta_group::1.mbarrier::arrive::one.shared::cluster.b64 [%0];" \
                 :: "r"(mbar) : "memory")
#define TC_WAIT_LD() asm volatile("tcgen05.wait::ld.sync.aligned;" ::: "memory")
#define TC_FENCE_AFTER() asm volatile("tcgen05.fence::after_thread_sync;" ::: "memory")
#define MBAR_INIT(mbar, cnt) \
    asm volatile("mbarrier.init.shared.b64 [%0], %1;" :: "r"(mbar), "r"(cnt) : "memory")

#define MBAR_WAIT(mbar, ph) do {                                              \
    uint32_t _done;                                                           \
    asm volatile("{\n\t.reg .pred p;\n\t"                                     \
        "mbarrier.try_wait.parity.acquire.cta.shared::cta.b64 p, [%1], %2;\n\t" \
        "selp.b32 %0,1,0,p;\n\t}"                                             \
        : "=r"(_done) : "r"(mbar), "r"(ph) : "memory");                       \
    if (!_done) {                                                             \
        asm volatile("{\n\t.reg .pred P1;\n\t"                                \
            "W1_%=:\n\t"                                                      \
            "mbarrier.try_wait.parity.acquire.cta.shared::cta.b64 P1, [%0], %1, 0x989680;\n\t" \
            "@P1 bra.uni W2_%=;\n\tbra.uni W1_%=;\n\tW2_%=:\n\t}"             \
            :: "r"(mbar), "r"(ph) : "memory");                                \
    }                                                                         \
} while (0)

#define TC_LD_X32(r, tmem)                                                    \
    asm volatile("tcgen05.ld.sync.aligned.32x32b.x32.b32 "                    \
        "{%0, %1, %2, %3, %4, %5, %6, %7, "                                   \
        " %8, %9, %10, %11, %12, %13, %14, %15, "                             \
        " %16, %17, %18, %19, %20, %21, %22, %23, "                           \
        " %24, %25, %26, %27, %28, %29, %30, %31}, [%32];"                    \
        : "=r"((r)[0]),  "=r"((r)[1]),  "=r"((r)[2]),  "=r"((r)[3]),          \
          "=r"((r)[4]),  "=r"((r)[5]),  "=r"((r)[6]),  "=r"((r)[7]),          \
          "=r"((r)[8]),  "=r"((r)[9]),  "=r"((r)[10]), "=r"((r)[11]),         \
          "=r"((r)[12]), "=r"((r)[13]), "=r"((r)[14]), "=r"((r)[15]),         \
          "=r"((r)[16]), "=r"((r)[17]), "=r"((r)[18]), "=r"((r)[19]),         \
          "=r"((r)[20]), "=r"((r)[21]), "=r"((r)[22]), "=r"((r)[23]),         \
          "=r"((r)[24]), "=r"((r)[25]), "=r"((r)[26]), "=r"((r)[27]),         \
          "=r"((r)[28]), "=r"((r)[29]), "=r"((r)[30]), "=r"((r)[31])          \
        : "r"(tmem))

__device__ __forceinline__ void mma_ss_f16(uint32_t d, uint64_t a, uint64_t b,
                                           uint32_t idesc, bool acc) {
    uint32_t e = acc ? 1u : 0u;
    asm volatile(
        "{\n\t.reg .pred p;\n\tsetp.ne.u32 p, %4, 0;\n\t"
        "tcgen05.mma.cta_group::1.kind::f16 [%0], %1, %2, %3, {%5,%5,%5,%5}, p;\n\t}"
        :: "r"(d), "l"(a), "l"(b), "r"(idesc), "r"(e), "r"(0u)
        : "memory");
}
#endif  // HAS_TCGEN05

// SW128 blocked-atom offset: atom = 8 rows x 64 bf16 (1024B), col-major atoms.
template <int ROWS>
__device__ __forceinline__ uint32_t sw_off(int r, int c) {
    uint32_t atom = (uint32_t)(r >> 3) + (uint32_t)(c >> 6) * (ROWS >> 3);
    uint32_t off = atom * 1024 + (r & 7) * 128 + (c & 63) * 2;
    return off ^ ((off >> 3) & 0x70);
}

__device__ __forceinline__ void split4(float4 v, unsigned long long& hi,
                                       unsigned long long& lo) {
    __nv_bfloat16 h0 = __float2bfloat16(v.x), h1 = __float2bfloat16(v.y);
    __nv_bfloat16 h2 = __float2bfloat16(v.z), h3 = __float2bfloat16(v.w);
    __nv_bfloat16 l0 = __float2bfloat16(v.x - __bfloat162float(h0));
    __nv_bfloat16 l1 = __float2bfloat16(v.y - __bfloat162float(h1));
    __nv_bfloat16 l2 = __float2bfloat16(v.z - __bfloat162float(h2));
    __nv_bfloat16 l3 = __float2bfloat16(v.w - __bfloat162float(h3));
    hi = (unsigned long long)__bfloat16_as_ushort(h0)
       | ((unsigned long long)__bfloat16_as_ushort(h1) << 16)
       | ((unsigned long long)__bfloat16_as_ushort(h2) << 32)
       | ((unsigned long long)__bfloat16_as_ushort(h3) << 48);
    lo = (unsigned long long)__bfloat16_as_ushort(l0)
       | ((unsigned long long)__bfloat16_as_ushort(l1) << 16)
       | ((unsigned long long)__bfloat16_as_ushort(l2) << 32)
       | ((unsigned long long)__bfloat16_as_ushort(l3) << 48);
}

// input loaders: fp32 direct, fp16 via convert
__device__ __forceinline__ float4 loadA4(const float* p) {
    return *(const float4*)p;
}
__device__ __forceinline__ float4 loadA4(const __half* p) {
    uint2 u = *(const uint2*)p;
    float2 a = __half22float2(*(__half2*)&u.x);
    float2 b = __half22float2(*(__half2*)&u.y);
    return make_float4(a.x, a.y, b.x, b.y);
}

// ---------------------------------------------------------------------------
// GEMM: C[r,:] = (half) dinv[r] * (A[r,:] @ W)   (A fp32 or fp16, C fp16)
// ---------------------------------------------------------------------------
template <int OUT, typename AT>
__global__ void __launch_bounds__(256) tc_gemm(
    const AT* __restrict__ A, const float* __restrict__ W,
    __half* __restrict__ C, const float* __restrict__ dinv, int n)
{
    extern __shared__ char smem[];
    constexpr int K = 128;
    const int tid = threadIdx.x;
    const int row0 = blockIdx.x * 128;

#if HAS_TCGEN05
    constexpr uint32_t A_HI = 1024;
    constexpr uint32_t A_LO = A_HI + 128 * 256;
    constexpr uint32_t B_HI = A_LO + 128 * 256;
    constexpr uint32_t B_LO = B_HI + OUT * 256;

    const uint32_t sb = smem_u32(smem);
    const int wid = tid >> 5, lane = tid & 31;

    if (wid == 0) TC_ALLOC(sb + 0, 128);
    __syncthreads();
    uint32_t tmem;
    asm volatile("ld.shared.b32 %0, [%1];" : "=r"(tmem) : "r"(sb + 0));

    // --- A tile: 2 threads per row, 64 cols each ---
    {
        int r = row0 + (tid >> 1);
        int c0 = (tid & 1) * 64;
        if (r < n) {
            const AT* src = &A[(size_t)r * K + c0];
#pragma unroll
            for (int c = 0; c < 64; c += 4) {
                unsigned long long hi, lo;
                split4(loadA4(src + c), hi, lo);
                uint32_t o = sw_off<128>(tid >> 1, c0 + c);
                *(unsigned long long*)(smem + A_HI + o) = hi;
                *(unsigned long long*)(smem + A_LO + o) = lo;
            }
        } else {
#pragma unroll
            for (int c = 0; c < 64; c += 4) {
                uint32_t o = sw_off<128>(tid >> 1, c0 + c);
                *(unsigned long long*)(smem + A_HI + o) = 0ull;
                *(unsigned long long*)(smem + A_LO + o) = 0ull;
            }
        }
    }

    // --- B tile: B[nrow][k] = W[k][nrow] (transpose load, hi/lo split) ---
    {
        int br, k0, kcnt;
        if (OUT == 128) { br = tid >> 1; k0 = (tid & 1) * 64; kcnt = 64; }
        else { br = tid & 63; k0 = (tid >> 6) * 32; kcnt = 32; }
#pragma unroll 4
        for (int k = k0; k < k0 + kcnt; k += 4) {
            float4 v = make_float4(W[(size_t)(k + 0) * OUT + br],
                                   W[(size_t)(k + 1) * OUT + br],
                                   W[(size_t)(k + 2) * OUT + br],
                                   W[(size_t)(k + 3) * OUT + br]);
            unsigned long long hi, lo;
            split4(v, hi, lo);
            uint32_t o = sw_off<OUT>(br, k);
            *(unsigned long long*)(smem + B_HI + o) = hi;
            *(unsigned long long*)(smem + B_LO + o) = lo;
        }
    }
    asm volatile("fence.proxy.async.shared::cta;" ::: "memory");
    __syncthreads();

    if (tid == 0) MBAR_INIT(sb + 8, 1);
    __syncthreads();

    if (wid == 0) {
        if (elect1()) {
            const uint64_t DB = (2ull << 61) | (1ull << 46) | (64ull << 32) | (1ull << 16);
            uint64_t dAhi = DB | (((sb + A_HI) >> 4) & 0x3FFF);
            uint64_t dAlo = DB | (((sb + A_LO) >> 4) & 0x3FFF);
            uint64_t dBhi = DB | (((sb + B_HI) >> 4) & 0x3FFF);
            uint64_t dBlo = DB | (((sb + B_LO) >> 4) & 0x3FFF);
            constexpr uint32_t idesc =
                (1u << 4) | (1u << 7) | (1u << 10) | ((OUT / 8) << 17) | (8u << 24);
            bool first = true;
#pragma unroll
            for (int s = 0; s < 8; s++) {
                uint64_t ao = (s < 4) ? (uint64_t)(s * 2) : (uint64_t)(1024 + (s - 4) * 2);
                uint64_t bo = (s < 4) ? (uint64_t)(s * 2) : (uint64_t)(OUT * 8 + (s - 4) * 2);
                mma_ss_f16(tmem, dAhi + ao, dBhi + bo, idesc, !first);
                first = false;
                mma_ss_f16(tmem, dAhi + ao, dBlo + bo, idesc, true);
                mma_ss_f16(tmem, dAlo + ao, dBhi + bo, idesc, true);
            }
            TC_COMMIT(sb + 8);
        }
    }

    MBAR_WAIT(sb + 8, 0);
    TC_FENCE_AFTER();

    // --- epilogue: 8 warps; warp w: rows (w%4)*32+lane, column half w/4 ---
    {
        constexpr int CH = OUT / 2;
        int sp = wid & 3, hf = wid >> 2;
        int r = row0 + sp * 32 + lane;
        float sc = (r < n) ? dinv[r] : 0.f;
#pragma unroll
        for (int ch = 0; ch < CH; ch += 32) {
            uint32_t rg[32];
            TC_LD_X32(rg, tmem + hf * CH + ch);
            TC_WAIT_LD();
            if (r < n) {
#pragma unroll
                for (int q = 0; q < 4; q++) {
                    uint32_t h2[4];
#pragma unroll
                    for (int j = 0; j < 4; j++) {
                        __half2 hh = __floats2half2_rn(
                            __uint_as_float(rg[q * 8 + j * 2 + 0]) * sc,
                            __uint_as_float(rg[q * 8 + j * 2 + 1]) * sc);
                        h2[j] = *(uint32_t*)&hh;
                    }
                    *(uint4*)&C[(size_t)r * OUT + hf * CH + ch + q * 8] =
                        make_uint4(h2[0], h2[1], h2[2], h2[3]);
                }
            }
        }
    }

    __syncthreads();
    if (wid == 0) {
        if (elect1())
            asm volatile("mbarrier.inval.shared.b64 [%0];" :: "r"(sb + 8) : "memory");
        TC_DEALLOC(tmem, 128);
    }

#else  // FFMA fallback (virtual-arch build), 256 threads, 128 rows/CTA
    constexpr int NTX = OUT / 8;
    constexpr int NTY = 256 / NTX;
    constexpr int RPT = 128 / NTY;
    float* As = (float*)smem;
    float* Bs = (float*)(smem + 8 * 128 * 4);

    const int tx = tid % NTX;
    const int ty = tid / NTX;

    float acc[RPT][8];
#pragma unroll
    for (int i = 0; i < RPT; i++)
#pragma unroll
        for (int j = 0; j < 8; j++) acc[i][j] = 0.f;

    for (int k0 = 0; k0 < K; k0 += 8) {
        int ar = tid >> 1, ac = (tid & 1) << 2;
        float4 av = make_float4(0.f, 0.f, 0.f, 0.f);
        if (row0 + ar < n)
            av = loadA4(&A[(size_t)(row0 + ar) * K + k0 + ac]);
        As[(ac + 0) * 128 + ar] = av.x;
        As[(ac + 1) * 128 + ar] = av.y;
        As[(ac + 2) * 128 + ar] = av.z;
        As[(ac + 3) * 128 + ar] = av.w;
#pragma unroll
        for (int i = tid; i < 8 * OUT; i += 256)
            Bs[i] = W[(size_t)(k0 + i / OUT) * OUT + (i % OUT)];
        __syncthreads();
#pragma unroll
        for (int k = 0; k < 8; k++) {
            float a[RPT], b[8];
#pragma unroll
            for (int i = 0; i < RPT; i++) a[i] = As[k * 128 + ty * RPT + i];
            *(float4*)&b[0] = *(float4*)&Bs[k * OUT + tx * 8];
            *(float4*)&b[4] = *(float4*)&Bs[k * OUT + tx * 8 + 4];
#pragma unroll
            for (int i = 0; i < RPT; i++)
#pragma unroll
                for (int j = 0; j < 8; j++) acc[i][j] += a[i] * b[j];
        }
        __syncthreads();
    }

#pragma unroll
    for (int i = 0; i < RPT; i++) {
        int r = row0 + ty * RPT + i;
        if (r < n) {
            float sc = dinv[r];
            uint32_t h2[4];
#pragma unroll
            for (int j = 0; j < 4; j++) {
                __half2 hh = __floats2half2_rn(acc[i][j * 2] * sc,
                                               acc[i][j * 2 + 1] * sc);
                h2[j] = *(uint32_t*)&hh;
            }
            *(uint4*)&C[(size_t)r * OUT + tx * 8] = make_uint4(h2[0], h2[1], h2[2], h2[3]);
        }
    }
#endif
}

// ---------------------------------------------------------------------------
// init: zero cnt + parallel dtype probe (block 0) + cursor reset
// ---------------------------------------------------------------------------
__global__ void init_kernel(const int* __restrict__ w, int nwords,
                            int* cnt, int n) {
    int i = blockIdx.x * blockDim.x + threadIdx.x;
    if (i < n) cnt[i] = 0;
    if (blockIdx.x == 0) {
        __shared__ int sacc;
        if (threadIdx.x == 0) sacc = 0;
        __syncthreads();
        int limit = nwords < 2048 ? nwords : 2048;
        int acc = 0;
        for (int j = 2 * threadIdx.x + 1; j < limit; j += 512) acc |= w[j];
        if (acc) atomicOr(&sacc, 1);
        __syncthreads();
        if (threadIdx.x == 0) {
            g_idx64 = (sacc == 0) ? 1 : 0;
            g_cursor = 0;
        }
    }
}

// histogram: reads only the dst portion of the edge words
__global__ void hist_kernel(const int* __restrict__ w, int* cnt, int E, int n) {
    int e = blockIdx.x * blockDim.x + threadIdx.x;
    if (e >= E) return;
    int d = g_idx64 ? w[2 * ((size_t)E + e)] : w[(size_t)E + e];
    if ((unsigned)d >= (unsigned)n) d = 0;
    atomicAdd(&cnt[d], 1);
}

// Order-free segment assignment + cursor seed + dinv.
__global__ void assign_kernel(const int* __restrict__ cnt, int* rowptr,
                              int* cur, float* dinv, int n) {
    int i = blockIdx.x * blockDim.x + threadIdx.x;
    if (i >= n) return;
    int c = cnt[i];
    int base = (c > 0) ? atomicAdd(&g_cursor, c) : 0;
    rowptr[i] = base;
    cur[i] = base;
    dinv[i] = rsqrtf(1.0f + (float)c);  // +1 self-loop
}

// scatter: re-decode raw words, place via per-node cursor (no intermediates)
__global__ void scatter_kernel(const int* __restrict__ w, int* cur,
                               int* sorted, int E, int n) {
    int e = blockIdx.x * blockDim.x + threadIdx.x;
    if (e >= E) return;
    int s, d;
    if (g_idx64) {
        s = w[2 * (size_t)e];
        d = w[2 * ((size_t)E + e)];
    } else {
        s = w[e];
        d = w[(size_t)E + e];
    }
    if ((unsigned)s >= (unsigned)n) s = 0;
    if ((unsigned)d >= (unsigned)n) d = 0;
    sorted[atomicAdd(&cur[d], 1)] = s;
}

// ---------------------------------------------------------------------------
// Fused aggregate: res[d] = f( dinv[d] * (sum_in h[src] + h[d]) + bias )
// h fp16 (prescaled); fp32 accum; 8-way edge unroll for MLP.
// ---------------------------------------------------------------------------
__device__ __forceinline__ void ld4h(const __half* p, float* f) {
    uint2 u = *(const uint2*)p;
    float2 a = __half22float2(*(__half2*)&u.x);
    float2 b = __half22float2(*(__half2*)&u.y);
    f[0] = a.x; f[1] = a.y; f[2] = b.x; f[3] = b.y;
}
__device__ __forceinline__ void ld2h(const __half* p, float* f) {
    uint32_t u = *(const uint32_t*)p;
    float2 a = __half22float2(*(__half2*)&u);
    f[0] = a.x; f[1] = a.y;
}
__device__ __forceinline__ void st4(float* p, float4 v) { *(float4*)p = v; }
__device__ __forceinline__ void st4(__half* p, float4 v) {
    __half2 p0 = __floats2half2_rn(v.x, v.y);
    __half2 p1 = __floats2half2_rn(v.z, v.w);
    *(uint2*)p = make_uint2(*(uint32_t*)&p0, *(uint32_t*)&p1);
}
__device__ __forceinline__ void st2(float* p, float2 v) { *(float2*)p = v; }
__device__ __forceinline__ void st2(__half* p, float2 v) {
    __half2 p0 = __floats2half2_rn(v.x, v.y);
    *(uint32_t*)p = *(uint32_t*)&p0;
}

template <int DIM, bool RELU, typename OT>
__global__ void __launch_bounds__(256) aggregate_kernel(
    const int* __restrict__ rowptr, const int* __restrict__ cnt,
    const int* __restrict__ sorted,
    const __half* __restrict__ h, OT* __restrict__ res,
    const float* __restrict__ dinv, const float* __restrict__ bias, int n)
{
    constexpr int VPL = DIM / 32;  // halves per lane: 4 (D=128) or 2 (D=64)
    int node = (int)((blockIdx.x * (long long)blockDim.x + threadIdx.x) >> 5);
    int lane = threadIdx.x & 31;
    if (node >= n) return;

    const int beg = rowptr[node];
    const int end = beg + cnt[node];
    const int col = lane * VPL;

    float acc[VPL];
    if (VPL == 4) ld4h(&h[(size_t)node * DIM + col], acc);
    else          ld2h(&h[(size_t)node * DIM + col], acc);

    int e = beg;
    for (; e + 8 <= end; e += 8) {
        int si[8];
#pragma unroll
        for (int u = 0; u < 8; u++) si[u] = sorted[e + u];
        float v[8][VPL];
#pragma unroll
        for (int u = 0; u < 8; u++) {
            if (VPL == 4) ld4h(&h[(size_t)si[u] * DIM + col], v[u]);
            else          ld2h(&h[(size_t)si[u] * DIM + col], v[u]);
        }
#pragma unroll
        for (int j = 0; j < VPL; j++)
            acc[j] += ((v[0][j] + v[1][j]) + (v[2][j] + v[3][j]))
                    + ((v[4][j] + v[5][j]) + (v[6][j] + v[7][j]));
    }
    for (; e < end; e++) {
        int s = sorted[e];
        float v[VPL];
        if (VPL == 4) ld4h(&h[(size_t)s * DIM + col], v);
        else          ld2h(&h[(size_t)s * DIM + col], v);
#pragma unroll
        for (int j = 0; j < VPL; j++) acc[j] += v[j];
    }

    float di = dinv[node];
    if (VPL == 4) {
        float4 b = *(const float4*)&bias[col];
        float4 r;
        r.x = di * acc[0] + b.x;
        r.y = di * acc[1] + b.y;
        r.z = di * acc[2] + b.z;
        r.w = di * acc[3] + b.w;
        if (RELU) {
            r.x = fmaxf(r.x, 0.f); r.y = fmaxf(r.y, 0.f);
            r.z = fmaxf(r.z, 0.f); r.w = fmaxf(r.w, 0.f);
        }
        st4(&res[(size_t)node * DIM + col], r);
    } else {
        float2 b = *(const float2*)&bias[col];
        float2 r;
        r.x = di * acc[0] + b.x;
        r.y = di * acc[1] + b.y;
        if (RELU) { r.x = fmaxf(r.x, 0.f); r.y = fmaxf(r.y, 0.f); }
        st2(&res[(size_t)node * DIM + col], r);
    }
}

// ---------------------------------------------------------------------------
// launch
// ---------------------------------------------------------------------------
static inline int cdiv(long long a, long long b) { return (int)((a + b - 1) / b); }

extern "C" void kernel_launch(void* const* d_in, const int* in_sizes, int n_in,
                              void* d_out, int out_size)
{
    const float* x   = (const float*)d_in[0];
    const int*   eiw = (const int*)d_in[1];
    const float* W1  = (const float*)d_in[2];
    const float* b1  = (const float*)d_in[3];
    const float* W2  = (const float*)d_in[4];
    const float* b2  = (const float*)d_in[5];
    float*       out = (float*)d_out;

    const int n = in_sizes[0] / D0;
    int E = in_sizes[1] / 2;
    if (E > EMAX) E = EMAX;

    float* dinv;
    __half *h, *agg;
    int *sorted, *cnt, *rowptr, *cur;
    cudaGetSymbolAddress((void**)&dinv,   g_dinv);
    cudaGetSymbolAddress((void**)&h,      g_h);
    cudaGetSymbolAddress((void**)&agg,    g_agg);
    cudaGetSymbolAddress((void**)&sorted, g_sorted);
    cudaGetSymbolAddress((void**)&cnt,    g_cnt);
    cudaGetSymbolAddress((void**)&rowptr, g_rowptr);
    cudaGetSymbolAddress((void**)&cur,    g_cur);

    constexpr int SMEM1 = 1024 + 2 * 128 * 256 + 2 * 128 * 256;
    constexpr int SMEM2 = 1024 + 2 * 128 * 256 + 2 * 64 * 256;
    cudaFuncSetAttribute(tc_gemm<128, float>,
                         cudaFuncAttributeMaxDynamicSharedMemorySize, SMEM1);
    cudaFuncSetAttribute(tc_gemm<64, __half>,
                         cudaFuncAttributeMaxDynamicSharedMemorySize, SMEM2);

    // --- CSR build (no edge-sized intermediates) ---
    init_kernel<<<cdiv(n, 256), 256>>>(eiw, in_sizes[1], cnt, n);
    hist_kernel<<<cdiv(E, 256), 256>>>(eiw, cnt, E, n);
    assign_kernel<<<cdiv(n, 256), 256>>>(cnt, rowptr, cur, dinv, n);
    scatter_kernel<<<cdiv(E, 256), 256>>>(eiw, cur, sorted, E, n);

    // --- layer 1 ---
    tc_gemm<D1, float><<<cdiv(n, 128), 256, SMEM1>>>(x, W1, h, dinv, n);
    aggregate_kernel<D1, true, __half><<<cdiv(n, 8), 256>>>(
        rowptr, cnt, sorted, h, agg, dinv, b1, n);

    // --- layer 2 ---
    tc_gemm<D2, __half><<<cdiv(n, 128), 256, SMEM2>>>(agg, W2, h, dinv, n);
    aggregate_kernel<D2, false, float><<<cdiv(n, 8), 256>>>(
        rowptr, cnt, sorted, h, out, dinv, b2, n);
}